// round 4
// baseline (speedup 1.0000x reference)
#include <cuda_runtime.h>
#include <cuda_bf16.h>

// Problem constants: B=1, H=2, S=128, D=64
#define Sdim 128
#define Ddim 64
#define Hdim 2
#define TWOD 128          // 2*D
#define DD   4096         // D*D
#define ROWS (Hdim * Sdim)   // 256 (h, s) pairs

typedef unsigned long long ull;

// Scratch: T stored TRANSPOSED [k=128][m=256]
__device__ float g_Tt[TWOD * ROWS];

__device__ __forceinline__ float tanh_approx(float x) {
    float y;
    asm("tanh.approx.f32 %0, %1;" : "=f"(y) : "f"(x));
    return y;
}
__device__ __forceinline__ ull fma2(ull a, ull b, ull c) {
    ull d;
    asm("fma.rn.f32x2 %0, %1, %2, %3;" : "=l"(d) : "l"(a), "l"(b), "l"(c));
    return d;
}
__device__ __forceinline__ ull pack2(float x, float y) {
    ull r;
    asm("mov.b64 %0, {%1, %2};" : "=l"(r) : "f"(x), "f"(y));
    return r;
}
__device__ __forceinline__ void unpack2(ull v, float& x, float& y) {
    asm("mov.b64 {%0, %1}, %2;" : "=f"(x), "=f"(y) : "l"(v));
}

// ---------------------------------------------------------------------------
// K12 (fused): one block per hidden column c.
//   A[r,c]  = Q[r,:]  . W1[0:64, c]
//   Bk[r,c] = K[r,:]  . W1[64:128, c] + b1[c]
//   Tt[c,r] = sum_i tanh(A[h(r)*128+i, c] + Bk[r,c])
// grid 128 x 256 threads. All W1/A/Bk traffic through smem; Q/K rows via
// 16 independent float4 loads per thread (high MLP). Output coalesced.
// ---------------------------------------------------------------------------
__global__ void __launch_bounds__(256, 4)
k12_fused(const float* __restrict__ Q, const float* __restrict__ Kin,
          const float* __restrict__ W1, const float* __restrict__ b1) {
    __shared__ float w1a[Ddim];     // W1[k, c],     k in [0,64)
    __shared__ float w1b[Ddim];     // W1[64+k, c]
    __shared__ float Acol[ROWS];
    __shared__ float Bkcol[ROWS];

    int c = blockIdx.x;             // hidden column
    int r = threadIdx.x;            // (h, s) row, 0..255

    if (r < TWOD) {
        float v = W1[r * TWOD + c];
        if (r < Ddim) w1a[r] = v;
        else          w1b[r - Ddim] = v;
    }
    __syncthreads();

    // Phase 1: per-row dot products (Q row and K row, 16 float4 each)
    {
        const float4* q4 = (const float4*)(Q + r * Ddim);
        const float4* k4 = (const float4*)(Kin + r * Ddim);
        float a0 = 0.f, a1 = 0.f, a2 = 0.f, a3 = 0.f;
        float bacc = b1[c];
        float b0 = 0.f, b1p = 0.f, b2p = 0.f, b3p = 0.f;
#pragma unroll
        for (int v = 0; v < 16; v++) {
            float4 q = q4[v];
            float4 k = k4[v];
            const float* wa = w1a + v * 4;
            const float* wb = w1b + v * 4;
            a0 = fmaf(q.x, wa[0], a0);
            a1 = fmaf(q.y, wa[1], a1);
            a2 = fmaf(q.z, wa[2], a2);
            a3 = fmaf(q.w, wa[3], a3);
            b0 = fmaf(k.x, wb[0], b0);
            b1p = fmaf(k.y, wb[1], b1p);
            b2p = fmaf(k.z, wb[2], b2p);
            b3p = fmaf(k.w, wb[3], b3p);
        }
        Acol[r] = (a0 + a1) + (a2 + a3);
        Bkcol[r] = bacc + (b0 + b1p) + (b2p + b3p);
    }
    __syncthreads();

    // Phase 2: T[c, r] = sum_i tanh(Acol[h*128+i] + Bkcol[r])
    {
        float bk = Bkcol[r];
        const float* Ab = Acol + ((r >> 7) << 7);   // h * 128
        float s0 = 0.f, s1 = 0.f, s2 = 0.f, s3 = 0.f;
#pragma unroll
        for (int i = 0; i < Sdim; i += 8) {
            float x0 = Ab[i + 0], x1 = Ab[i + 1], x2 = Ab[i + 2], x3 = Ab[i + 3];
            float x4 = Ab[i + 4], x5 = Ab[i + 5], x6 = Ab[i + 6], x7 = Ab[i + 7];
            s0 += tanh_approx(x0 + bk);
            s1 += tanh_approx(x1 + bk);
            s2 += tanh_approx(x2 + bk);
            s3 += tanh_approx(x3 + bk);
            s0 += tanh_approx(x4 + bk);
            s1 += tanh_approx(x5 + bk);
            s2 += tanh_approx(x6 + bk);
            s3 += tanh_approx(x7 + bk);
        }
        g_Tt[c * ROWS + r] = (s0 + s1) + (s2 + s3);   // coalesced
    }
}

// ---------------------------------------------------------------------------
// K3 (fused, f32x2): tile of U = T @ W2 in packed-pair registers, contracted
// against K in epilogue:
//   out[m, d=bn] = sum_e (Utile[m,e]/S + b2[d*64+e]) * K[m,e]
// M=256, N=4096, K=128.  BM=64, BN=64 (one d per block), BK=32.
// T comes in pre-transposed (g_Tt[k][m]) so staging is a straight copy.
// 128 threads: tx in [0,16) -> 4 e-cols; ty in [0,8) -> 8 m-rows (4 pairs).
// grid: (64, 4).
// ---------------------------------------------------------------------------
#define KSTRIDE 68

__global__ void __launch_bounds__(128, 4)
k3_gemm_fused(const float* __restrict__ W2,
              const float* __restrict__ Kin,
              const float* __restrict__ b2,
              float* __restrict__ out) {
    __shared__ float Tst[32 * 64];        // [kk][m] T tile (direct copy)
    __shared__ float Ws [32 * 64];        // [kk][n]
    __shared__ float Kst[64 * KSTRIDE];   // [e][m] transposed K rows
    int bm = blockIdx.y, bn = blockIdx.x;
    int tid = threadIdx.x;                // 0..127
    int tx = tid & 15;                    // e-group (4 cols)
    int ty = tid >> 4;                    // m-group (8 rows)

    // Stage K rows (transposed): 64 m x 64 e
#pragma unroll
    for (int v = 0; v < 8; v++) {
        int i4 = tid + v * 128;           // 1024 float4
        int m = i4 >> 4, e4 = i4 & 15;
        float4 f = *(const float4*)(Kin + (bm * 64 + m) * Ddim + e4 * 4);
        Kst[(e4 * 4 + 0) * KSTRIDE + m] = f.x;
        Kst[(e4 * 4 + 1) * KSTRIDE + m] = f.y;
        Kst[(e4 * 4 + 2) * KSTRIDE + m] = f.z;
        Kst[(e4 * 4 + 3) * KSTRIDE + m] = f.w;
    }

    ull acc[4][4];
#pragma unroll
    for (int p = 0; p < 4; p++)
#pragma unroll
        for (int c = 0; c < 4; c++) acc[p][c] = 0ull;

#pragma unroll
    for (int kt = 0; kt < 4; kt++) {
        // stage T tile: direct copy from transposed global layout
#pragma unroll
        for (int v = 0; v < 4; v++) {
            int i4 = tid + v * 128;       // 512 float4
            int kk = i4 >> 4, m4 = i4 & 15;
            ((float4*)(Tst + kk * 64))[m4] =
                *(const float4*)(g_Tt + (kt * 32 + kk) * ROWS + bm * 64 + m4 * 4);
        }
        // stage W2 tile: 32 k x 64 n (row-major)
#pragma unroll
        for (int v = 0; v < 4; v++) {
            int i4 = tid + v * 128;       // 512 float4
            int kk = i4 >> 4, n4 = i4 & 15;
            ((float4*)Ws)[i4] =
                *(const float4*)(W2 + (kt * 32 + kk) * DD + bn * 64 + n4 * 4);
        }
        __syncthreads();

#pragma unroll
        for (int kk = 0; kk < 32; kk++) {
            const float* trow = Tst + kk * 64 + ty * 8;
            ull a0 = *(const ull*)(trow + 0);   // (m0,m1)
            ull a1 = *(const ull*)(trow + 2);
            ull a2 = *(const ull*)(trow + 4);
            ull a3 = *(const ull*)(trow + 6);
            float4 bv = *(const float4*)(Ws + kk * 64 + tx * 4);
            ull b0 = pack2(bv.x, bv.x);
            ull b1 = pack2(bv.y, bv.y);
            ull b2p = pack2(bv.z, bv.z);
            ull b3 = pack2(bv.w, bv.w);
            acc[0][0] = fma2(a0, b0, acc[0][0]);
            acc[0][1] = fma2(a0, b1, acc[0][1]);
            acc[0][2] = fma2(a0, b2p, acc[0][2]);
            acc[0][3] = fma2(a0, b3, acc[0][3]);
            acc[1][0] = fma2(a1, b0, acc[1][0]);
            acc[1][1] = fma2(a1, b1, acc[1][1]);
            acc[1][2] = fma2(a1, b2p, acc[1][2]);
            acc[1][3] = fma2(a1, b3, acc[1][3]);
            acc[2][0] = fma2(a2, b0, acc[2][0]);
            acc[2][1] = fma2(a2, b1, acc[2][1]);
            acc[2][2] = fma2(a2, b2p, acc[2][2]);
            acc[2][3] = fma2(a2, b3, acc[2][3]);
            acc[3][0] = fma2(a3, b0, acc[3][0]);
            acc[3][1] = fma2(a3, b1, acc[3][1]);
            acc[3][2] = fma2(a3, b2p, acc[3][2]);
            acc[3][3] = fma2(a3, b3, acc[3][3]);
        }
        __syncthreads();
    }

    // Epilogue: v = acc/S + b2 ; pairwise dot with K over e; 16-lane reduce.
    const float invS = 1.0f / (float)Sdim;
    ull invS2 = pack2(invS, invS);
    float4 bbv = *(const float4*)(b2 + bn * 64 + tx * 4);
    ull bb[4] = { pack2(bbv.x, bbv.x), pack2(bbv.y, bbv.y),
                  pack2(bbv.z, bbv.z), pack2(bbv.w, bbv.w) };
#pragma unroll
    for (int p = 0; p < 4; p++) {
        ull sum = 0ull;
#pragma unroll
        for (int c = 0; c < 4; c++) {
            ull v = fma2(acc[p][c], invS2, bb[c]);
            ull kv = *(const ull*)(Kst + (tx * 4 + c) * KSTRIDE + ty * 8 + 2 * p);
            sum = fma2(v, kv, sum);
        }
        float s0, s1;
        unpack2(sum, s0, s1);
#pragma unroll
        for (int off = 1; off < 16; off <<= 1) {
            s0 += __shfl_xor_sync(0xffffffffu, s0, off, 32);
            s1 += __shfl_xor_sync(0xffffffffu, s1, off, 32);
        }
        if (tx == 0) {
            int m0 = bm * 64 + ty * 8 + 2 * p;
            out[m0 * Ddim + bn] = s0;
            out[(m0 + 1) * Ddim + bn] = s1;
        }
    }
}

// ---------------------------------------------------------------------------
extern "C" void kernel_launch(void* const* d_in, const int* in_sizes, int n_in,
                              void* d_out, int out_size) {
    const float* Q   = (const float*)d_in[0];
    const float* Kin = (const float*)d_in[1];
    const float* W1  = (const float*)d_in[2];
    const float* b1  = (const float*)d_in[3];
    const float* W2  = (const float*)d_in[4];
    const float* b2  = (const float*)d_in[5];
    float* out = (float*)d_out;

    k12_fused<<<TWOD, ROWS>>>(Q, Kin, W1, b1);
    k3_gemm_fused<<<dim3(Ddim, ROWS / 64), 128>>>(W2, Kin, b2, out);
}